// round 11
// baseline (speedup 1.0000x reference)
#include <cuda_runtime.h>

// Pixel-wise diagonal RNN:
//   h_t = leaky_relu(W_ih * x_t + W_hh * h_{t-1} + b_hh), h_0 = 0
// Streaming-bound. R10 baseline: 133.2us @ DRAM 78.4% (in-flight loads
// limited by registers). This version stages x through smem with per-thread
// cp.async pipelines: in-flight bytes come from smem (6 stages x 32B/thread),
// NOT registers, and no __syncthreads is needed because every thread consumes
// only its own staged data (cp.async.wait_group is per-thread).

#ifndef NEG_SLOPE
#define NEG_SLOPE 0.01f
#endif

#define STAGES 6

__device__ __forceinline__ unsigned smem_u32(const void* p) {
    return (unsigned)__cvta_generic_to_shared(p);
}

__device__ __forceinline__ float4 rnn_step(float4 wi, float4 wh, float4 b,
                                           float4 xv, float4 h)
{
    float4 v;
    v.x = fmaf(wi.x, xv.x, fmaf(wh.x, h.x, b.x));
    v.y = fmaf(wi.y, xv.y, fmaf(wh.y, h.y, b.y));
    v.z = fmaf(wi.z, xv.z, fmaf(wh.z, h.z, b.z));
    v.w = fmaf(wi.w, xv.w, fmaf(wh.w, h.w, b.w));
    float4 r;
    r.x = fmaxf(v.x, NEG_SLOPE * v.x);
    r.y = fmaxf(v.y, NEG_SLOPE * v.y);
    r.z = fmaxf(v.z, NEG_SLOPE * v.z);
    r.w = fmaxf(v.w, NEG_SLOPE * v.w);
    return r;
}

__global__ __launch_bounds__(256) void pixelwise_rnn_kernel(
    const float4* __restrict__ x,     // (T, P/4)
    const float4* __restrict__ w_ih,  // (P/4)
    const float4* __restrict__ w_hh,  // (P/4)
    const float4* __restrict__ b_hh,  // (P/4)
    float4* __restrict__ out,         // (T, P/4)
    int P4, int T)
{
    // Block owns 512 contiguous float4s; thread owns q0 = base+tid and
    // q1 = q0+256 so each cp.async instruction is a contiguous 512B/warp.
    __shared__ float4 sm[STAGES][512];   // 48 KB

    int tid = threadIdx.x;
    int q0 = blockIdx.x * 512 + tid;
    int q1 = q0 + 256;

    const float4 wi0 = w_ih[q0], wi1 = w_ih[q1];
    const float4 wh0 = w_hh[q0], wh1 = w_hh[q1];
    const float4 b0  = b_hh[q0], b1  = b_hh[q1];

    float4 h0 = make_float4(0.f, 0.f, 0.f, 0.f);
    float4 h1 = make_float4(0.f, 0.f, 0.f, 0.f);

    const float4* xp0 = x + q0;
    const float4* xp1 = x + q1;
    float4* op0 = out + q0;
    float4* op1 = out + q1;

    // Prologue: issue stages for t = 0 .. STAGES-2 (one commit group each).
    #pragma unroll
    for (int s = 0; s < STAGES - 1; ++s) {
        size_t off = (size_t)s * P4;
        unsigned d0 = smem_u32(&sm[s][tid]);
        unsigned d1 = smem_u32(&sm[s][tid + 256]);
        asm volatile("cp.async.cg.shared.global [%0], [%1], 16;" :: "r"(d0), "l"(xp0 + off));
        asm volatile("cp.async.cg.shared.global [%0], [%1], 16;" :: "r"(d1), "l"(xp1 + off));
        asm volatile("cp.async.commit_group;");
    }

    for (int t = 0; t < T; ++t) {
        // Prefetch stage t+STAGES-1 (always commit a group, possibly empty,
        // so group counting stays uniform).
        int tp = t + STAGES - 1;
        if (tp < T) {
            int s = tp % STAGES;
            size_t off = (size_t)tp * P4;
            unsigned d0 = smem_u32(&sm[s][tid]);
            unsigned d1 = smem_u32(&sm[s][tid + 256]);
            asm volatile("cp.async.cg.shared.global [%0], [%1], 16;" :: "r"(d0), "l"(xp0 + off));
            asm volatile("cp.async.cg.shared.global [%0], [%1], 16;" :: "r"(d1), "l"(xp1 + off));
        }
        asm volatile("cp.async.commit_group;");

        // Wait until at most STAGES-2 newest groups are pending:
        // group for timestep t (and t+1) is then complete for THIS thread.
        asm volatile("cp.async.wait_group %0;" :: "n"(STAGES - 2));

        int s = t % STAGES;
        float4 xv0 = sm[s][tid];
        float4 xv1 = sm[s][tid + 256];

        h0 = rnn_step(wi0, wh0, b0, xv0, h0);
        h1 = rnn_step(wi1, wh1, b1, xv1, h1);

        size_t off = (size_t)t * P4;
        __stcs(op0 + off, h0);
        __stcs(op1 + off, h1);
    }
}

extern "C" void kernel_launch(void* const* d_in, const int* in_sizes, int n_in,
                              void* d_out, int out_size)
{
    const float* x    = (const float*)d_in[0];  // (B=1, T, Z, H, W)
    const float* w_ih = (const float*)d_in[1];  // (Z, H, W)
    const float* w_hh = (const float*)d_in[2];
    const float* b_hh = (const float*)d_in[3];
    float* out = (float*)d_out;

    int P = in_sizes[1];            // Z*H*W = 2097152
    int T = in_sizes[0] / P;        // 50
    int P4 = P / 4;                 // 524288

    int threads = 256;
    int blocks = P4 / 512;          // 1024 blocks, 512 float4 per block
    pixelwise_rnn_kernel<<<blocks, threads>>>(
        (const float4*)x, (const float4*)w_ih, (const float4*)w_hh,
        (const float4*)b_hh, (float4*)out, P4, T);
}